// round 3
// baseline (speedup 1.0000x reference)
#include <cuda_runtime.h>

#define BB 4
#define NT 256
#define NZ 384
#define NXX 384
#define NREC 128
#define DTc 0.001f
#define DHc 10.0f

#define NBLK 128
#define BLK_PER_B (NBLK / BB)      // 32 blocks per batch
#define ROWS (NZ / BLK_PER_B)      // 12 owned rows per block
#define S 4                        // temporal block depth (exchange every S steps)
#define EXT (ROWS + 2 * S)         // 20 tile rows (incl. ghosts)
#define NTHR 512
#define EPTS (EXT * NXX)           // 7680 tile points
#define PPT (EPTS / NTHR)          // 15 points per thread
#define NSWEEP (NT / S)            // 64 sweeps

// Exchange state. flags[blk] = number of exchanges this block has published.
__device__ int   d_flags[NBLK];
// [slot][block][side:0=top-owned rows,1=bottom-owned rows][level:0=u(t-1),1=u(t-2)][S][x]
__device__ float d_halo[2][NBLK][2][2][S][NXX];

__global__ void zero_kernel() {
    int i = blockIdx.x * blockDim.x + threadIdx.x;
    if (i < NBLK) d_flags[i] = 0;
}

extern __shared__ float sbuf[];   // [2][EXT*NXX] double-buffered field tile

__global__ __launch_bounds__(NTHR) void wave_kernel(
    const float* __restrict__ xsrc,   // [B, NT]
    const float* __restrict__ vp,     // [NZ, NX]
    const int*   __restrict__ src_y,
    const int*   __restrict__ src_x,
    const int*   __restrict__ rec_y,
    const int*   __restrict__ rec_x,
    float*       __restrict__ out)    // [NT, B, NREC]
{
    float* sb0 = sbuf;
    float* sb1 = sbuf + EPTS;

    const int tid = threadIdx.x;
    const int blk = blockIdx.x;
    const int b   = blk / BLK_PER_B;
    const int bib = blk % BLK_PER_B;
    const int z0  = bib * ROWS;         // first owned global row
    const int tz0 = z0 - S;             // global row of tile row 0 (may be <0)
    const float inv_dh2 = 1.0f / (DHc * DHc);

    const int topBlk = (bib > 0) ? blk - 1 : -1;
    const int botBlk = (bib < BLK_PER_B - 1) ? blk + 1 : -1;

    const int sy = src_y[b];
    const int sx = src_x[b];

    // ---- per-slot init ----
    float ucur[PPT];   // u(t-1) at my points
    float uprev[PPT];  // u(t-2) at my points
    float c2[PPT];     // (vp*DT)^2
    int   zgarr[PPT];
    int   smask = 0;   // source bit per slot
    int   lapok = 0;   // interior-laplacian bit per slot
    int   gmask = 0;   // ghost-slot bit (needs reg refresh after exchange)

#pragma unroll
    for (int j = 0; j < PPT; j++) {
        const int p   = tid + j * NTHR;
        const int row = p / NXX;
        const int col = p % NXX;
        const int zg  = tz0 + row;
        zgarr[j] = zg;
        ucur[j]  = 0.0f;
        uprev[j] = 0.0f;
        c2[j]    = 0.0f;
        if (zg >= 0 && zg < NZ) {
            const float c = vp[zg * NXX + col] * DTc;
            c2[j] = c * c;
            if (zg == sy && col == sx) smask |= (1 << j);
            if (col > 0 && col < NXX - 1 && zg > 0 && zg < NZ - 1) lapok |= (1 << j);
            if (zg < z0 || zg >= z0 + ROWS) gmask |= (1 << j);
        }
        sb0[p] = 0.0f;
        sb1[p] = 0.0f;
    }

    int   rmine = 0, roff = 0, obase = 0;
    if (tid < NREC) {
        const int ry = rec_y[tid];
        const int rx = rec_x[tid];
        rmine = (ry >= z0 && ry < z0 + ROWS);
        roff  = (ry - tz0) * NXX + rx;
        obase = b * NREC + tid;
    }
    const float* xs = xsrc + b * NT;

    __syncthreads();

    for (int e = 0; e < NSWEEP; e++) {
        // ================= exchange (skip e=0: field is all zero) =================
        if (e > 0) {
            const int slot = e & 1;
            // publish my boundary rows, both time levels (sb0=u(t-1), sb1=u(t-2))
            for (int i = tid; i < 2 * S * NXX; i += NTHR) {
                const int L = i / (S * NXX);
                const int r = (i / NXX) % S;
                const int x = i % NXX;
                const float* sl = L ? sb1 : sb0;
                if (topBlk >= 0)
                    __stcg(&d_halo[slot][blk][0][L][r][x], sl[(S + r) * NXX + x]);
                if (botBlk >= 0)
                    __stcg(&d_halo[slot][blk][1][L][r][x], sl[(ROWS + r) * NXX + x]);
            }
            __threadfence();
            __syncthreads();
            if (tid == 0) {
                *((volatile int*)&d_flags[blk]) = e;
                if (topBlk >= 0)
                    while (*((volatile int*)&d_flags[topBlk]) < e) { }
                if (botBlk >= 0)
                    while (*((volatile int*)&d_flags[botBlk]) < e) { }
                __threadfence();
            }
            __syncthreads();
            // load ghosts from neighbors
            for (int i = tid; i < 2 * S * NXX; i += NTHR) {
                const int L = i / (S * NXX);
                const int r = (i / NXX) % S;
                const int x = i % NXX;
                float* sl = L ? sb1 : sb0;
                if (topBlk >= 0)
                    sl[r * NXX + x] = __ldcg(&d_halo[slot][topBlk][1][L][r][x]);
                if (botBlk >= 0)
                    sl[(ROWS + S + r) * NXX + x] = __ldcg(&d_halo[slot][botBlk][0][L][r][x]);
            }
            __syncthreads();
            // refresh register copies on ghost slots
#pragma unroll
            for (int j = 0; j < PPT; j++) {
                if (gmask & (1 << j)) {
                    const int p = tid + j * NTHR;
                    ucur[j]  = sb0[p];
                    uprev[j] = sb1[p];
                }
            }
        }

        // ================= S substeps =================
#pragma unroll
        for (int k = 0; k < S; k++) {
            const int t  = e * S + k;
            const int rd = t & 1;                 // buffer holding u(t-1)
            float* __restrict__ rbuf = rd ? sb1 : sb0;
            float* __restrict__ wbuf = rd ? sb0 : sb1;

            const int lo = (topBlk < 0) ? 0  : (z0 - S + 1 + k);
            const int hi = (botBlk < 0) ? NZ : (z0 + ROWS + S - 1 - k);
            const float xt = xs[t];

#pragma unroll
            for (int j = 0; j < PPT; j++) {
                const int zg = zgarr[j];
                if (zg < lo || zg >= hi) continue;
                const int p = tid + j * NTHR;
                float lap = 0.0f;
                if (lapok & (1 << j)) {
                    lap = (rbuf[p - NXX] + rbuf[p + NXX] +
                           rbuf[p - 1]   + rbuf[p + 1]   -
                           4.0f * ucur[j]) * inv_dh2;
                }
                float hn = 2.0f * ucur[j] - uprev[j] + c2[j] * lap;
                if (smask & (1 << j)) hn += xt;
                uprev[j] = ucur[j];
                ucur[j]  = hn;
                wbuf[p]  = hn;
            }
            __syncthreads();
            // receiver gather for step t (u(t) now complete in wbuf)
            if (tid < NREC && rmine) {
                out[t * (BB * NREC) + obase] = wbuf[roff];
            }
        }
    }
}

extern "C" void kernel_launch(void* const* d_in, const int* in_sizes, int n_in,
                              void* d_out, int out_size)
{
    const float* xsrc  = (const float*)d_in[0];
    const float* vp    = (const float*)d_in[1];
    const int*   src_y = (const int*)d_in[2];
    const int*   src_x = (const int*)d_in[3];
    const int*   rec_y = (const int*)d_in[4];
    const int*   rec_x = (const int*)d_in[5];
    float*       out   = (float*)d_out;

    const int smem_bytes = 2 * EPTS * (int)sizeof(float);   // 61440
    static int configured = 0;
    if (!configured) {
        cudaFuncSetAttribute(wave_kernel,
                             cudaFuncAttributeMaxDynamicSharedMemorySize,
                             smem_bytes);
        configured = 1;
    }

    zero_kernel<<<1, NBLK>>>();
    wave_kernel<<<NBLK, NTHR, smem_bytes>>>(xsrc, vp, src_y, src_x,
                                            rec_y, rec_x, out);
}

// round 5
// speedup vs baseline: 1.4142x; 1.4142x over previous
#include <cuda_runtime.h>

#define BB 4
#define NT 256
#define NZ 384
#define NXX 384
#define NREC 128
#define DTc 0.001f
#define DHc 10.0f

#define NBLK 128
#define BLK_PER_B (NBLK / BB)      // 32 blocks per batch
#define ROWS 12                    // owned rows per block
#define RPT 6                      // rows per thread (2 halves)
#define NTHR (2 * NXX)             // 768 threads: thread = (column, half)

// Per-step neighbor sync. flags[blk] = t+1 after block published u(t-1) halos.
__device__ int   d_flags[NBLK];
__device__ float d_halo[2][NBLK][2][NXX];   // [slot][block][0=top row,1=bot row][x]

__global__ void zero_kernel() {
    int i = threadIdx.x;
    if (i < NBLK) d_flags[i] = 0;
}

__global__ __launch_bounds__(NTHR, 1) void wave_kernel(
    const float* __restrict__ xsrc,   // [B, NT]
    const float* __restrict__ vp,     // [NZ, NX]
    const int*   __restrict__ src_y,
    const int*   __restrict__ src_x,
    const int*   __restrict__ rec_y,
    const int*   __restrict__ rec_x,
    float*       __restrict__ out)    // [NT, B, NREC]
{
    __shared__ float stile[ROWS * NXX];     // u(t-1) tile, written ONLY in Phase A

    const int tid  = threadIdx.x;
    const int x    = tid % NXX;
    const int half = tid / NXX;             // 0: rows 0-5, 1: rows 6-11
    const int blk  = blockIdx.x;
    const int b    = blk / BLK_PER_B;
    const int bib  = blk % BLK_PER_B;
    const int z0   = bib * ROWS;
    const int rowbase = half * RPT;         // local row of k=0
    const float inv_dh2 = 1.0f / (DHc * DHc);

    const int topBlk = (bib > 0) ? blk - 1 : -1;
    const int botBlk = (bib < BLK_PER_B - 1) ? blk + 1 : -1;

    // this thread publishes a halo row?
    const bool pubTop = (half == 0) && (topBlk >= 0);
    const bool pubBot = (half == 1) && (botBlk >= 0);

    const int sy = src_y[b];
    const int sx = src_x[b];

    float ucur[RPT], uprev[RPT], c2[RPT];
    unsigned lapok = 0, smask = 0;

#pragma unroll
    for (int k = 0; k < RPT; k++) {
        const int zg = z0 + rowbase + k;
        ucur[k]  = 0.0f;
        uprev[k] = 0.0f;
        const float c = vp[zg * NXX + x] * DTc;
        c2[k] = c * c;
        if (x > 0 && x < NXX - 1 && zg > 0 && zg < NZ - 1) lapok |= (1u << k);
        if (zg == sy && x == sx) smask |= (1u << k);
    }

    // receiver bookkeeping
    int rmine = 0, roff = 0, obase = 0;
    if (tid < NREC) {
        const int ry = rec_y[tid];
        const int rx = rec_x[tid];
        rmine = (ry >= z0 && ry < z0 + ROWS);
        roff  = (ry - z0) * NXX + rx;
        obase = b * NREC + tid;
    }
    const float* xs = xsrc + b * NT;

    for (int t = 0; t < NT; t++) {
        const int slot = t & 1;

        // ---- Phase A: stage u(t-1) in smem, publish boundary rows ----
#pragma unroll
        for (int k = 0; k < RPT; k++)
            stile[(rowbase + k) * NXX + x] = ucur[k];
        if (pubTop) {
            __stcg(&d_halo[slot][blk][0][x], ucur[0]);
            __threadfence();
        }
        if (pubBot) {
            __stcg(&d_halo[slot][blk][1][x], ucur[RPT - 1]);
            __threadfence();
        }
        __syncthreads();
        if (tid == 0)
            *((volatile int*)&d_flags[blk]) = t + 1;

        // receiver gather for step t-1 (stile now holds u(t-1))
        if (t > 0 && tid < NREC && rmine)
            out[(t - 1) * (BB * NREC) + obase] = stile[roff];

        const float xt = xs[t];

        // ---- Phase B: interior rows; vertical up-neighbor via OLD-value carry ----
        {
            float carry = ucur[0];   // old value of row processed previously
#pragma unroll
            for (int k = 0; k < RPT; k++) {
                const bool isb = (half == 0) ? (k == 0) : (k == RPT - 1);
                if (isb) continue;   // boundary handled in Phase D
                const int srow = rowbase + k;
                const float uk = ucur[k];
                float lap = 0.0f;
                if (lapok & (1u << k)) {
                    const float up = (k > 0)       ? carry            // old u(t-1)[k-1]
                                                   : stile[(srow - 1) * NXX + x];
                    const float dn = (k < RPT - 1) ? ucur[k + 1]      // not yet updated
                                                   : stile[(srow + 1) * NXX + x];
                    lap = (up + dn + stile[srow * NXX + x - 1]
                                   + stile[srow * NXX + x + 1]
                                   - 4.0f * uk) * inv_dh2;
                }
                float hn = 2.0f * uk - uprev[k] + c2[k] * lap;
                if (smask & (1u << k)) hn += xt;
                uprev[k] = uk;
                ucur[k]  = hn;
                carry    = uk;       // old value for next iteration
            }
        }

        // ---- Phase C: wait for neighbors' u(t-1) halos ----
        if (tid == 0 && topBlk >= 0) {
            while (*((volatile int*)&d_flags[topBlk]) < t + 1) { }
            __threadfence();
        }
        if (tid == NXX && botBlk >= 0) {
            while (*((volatile int*)&d_flags[botBlk]) < t + 1) { }
            __threadfence();
        }
        __syncthreads();

        // ---- Phase D: boundary row; inner neighbor from stile (u(t-1)) ----
        {
            const int k    = (half == 0) ? 0 : RPT - 1;
            const int srow = rowbase + k;
            const float uk = ucur[k];
            float lap = 0.0f;
            if (lapok & (1u << k)) {
                float up, dn;
                if (half == 0) {
                    up = __ldcg(&d_halo[slot][topBlk][1][x]);   // lapok => topBlk>=0
                    dn = stile[(srow + 1) * NXX + x];           // u(t-1), untouched
                } else {
                    up = stile[(srow - 1) * NXX + x];           // u(t-1), untouched
                    dn = __ldcg(&d_halo[slot][botBlk][0][x]);   // lapok => botBlk>=0
                }
                lap = (up + dn + stile[srow * NXX + x - 1]
                               + stile[srow * NXX + x + 1]
                               - 4.0f * uk) * inv_dh2;
            }
            float hn = 2.0f * uk - uprev[k] + c2[k] * lap;
            if (smask & (1u << k)) hn += xt;
            uprev[k] = uk;
            ucur[k]  = hn;
        }
        __syncthreads();   // stile reads done before next step's Phase A overwrite
    }

    // ---- final receiver gather for t = NT-1 ----
#pragma unroll
    for (int k = 0; k < RPT; k++)
        stile[(rowbase + k) * NXX + x] = ucur[k];
    __syncthreads();
    if (tid < NREC && rmine)
        out[(NT - 1) * (BB * NREC) + obase] = stile[roff];
}

extern "C" void kernel_launch(void* const* d_in, const int* in_sizes, int n_in,
                              void* d_out, int out_size)
{
    const float* xsrc  = (const float*)d_in[0];
    const float* vp    = (const float*)d_in[1];
    const int*   src_y = (const int*)d_in[2];
    const int*   src_x = (const int*)d_in[3];
    const int*   rec_y = (const int*)d_in[4];
    const int*   rec_x = (const int*)d_in[5];
    float*       out   = (float*)d_out;

    zero_kernel<<<1, NBLK>>>();
    wave_kernel<<<NBLK, NTHR>>>(xsrc, vp, src_y, src_x, rec_y, rec_x, out);
}

// round 6
// speedup vs baseline: 1.4645x; 1.0356x over previous
#include <cuda_runtime.h>

#define BB 4
#define NT 256
#define NZ 384
#define NXX 384
#define NREC 128
#define DTc 0.001f
#define DHc 10.0f

#define NBLK 128
#define BLK_PER_B (NBLK / BB)      // 32 blocks per batch
#define ROWS 12                    // owned rows per block
#define RPT 6                      // rows per thread (2 halves)
#define NTHR (2 * NXX)             // 768 threads: thread = (column x, half)

// flags[blk] = t+1 once block published its u(t) boundary rows.
__device__ int   d_flags[NBLK];
__device__ float d_halo[2][NBLK][2][NXX];   // [t&1][block][0=row0,1=row11][x]

__global__ void zero_kernel() {
    int i = threadIdx.x;
    if (i < NBLK) d_flags[i] = 0;
}

__global__ __launch_bounds__(NTHR, 1) void wave_kernel(
    const float* __restrict__ xsrc,   // [B, NT]
    const float* __restrict__ vp,     // [NZ, NX]
    const int*   __restrict__ src_y,
    const int*   __restrict__ src_x,
    const int*   __restrict__ rec_y,
    const int*   __restrict__ rec_x,
    float*       __restrict__ out)    // [NT, B, NREC]
{
    __shared__ float sb0[ROWS * NXX];   // double-buffered field tile
    __shared__ float sb1[ROWS * NXX];

    const int tid  = threadIdx.x;
    const int x    = tid % NXX;
    const int half = tid / NXX;             // 0: rows 0-5, 1: rows 6-11
    const int blk  = blockIdx.x;
    const int b    = blk / BLK_PER_B;
    const int bib  = blk % BLK_PER_B;
    const int z0   = bib * ROWS;
    const int rowbase = half * RPT;
    const float inv_dh2 = 1.0f / (DHc * DHc);

    const int topBlk = (bib > 0) ? blk - 1 : -1;
    const int botBlk = (bib < BLK_PER_B - 1) ? blk + 1 : -1;
    // my outward neighbor (the one my boundary row touches)
    const int nb     = (half == 0) ? topBlk : botBlk;
    const bool hasNb = (nb >= 0);

    const int sy = src_y[b];
    const int sx = src_x[b];

    float ucur[RPT], uprev[RPT], c2[RPT];
    unsigned lapok = 0, smask = 0;

#pragma unroll
    for (int k = 0; k < RPT; k++) {
        const int zg = z0 + rowbase + k;
        ucur[k]  = 0.0f;
        uprev[k] = 0.0f;
        const float c = vp[zg * NXX + x] * DTc;
        c2[k] = c * c;
        if (x > 0 && x < NXX - 1 && zg > 0 && zg < NZ - 1) lapok |= (1u << k);
        if (zg == sy && x == sx) smask |= (1u << k);
        sb0[(rowbase + k) * NXX + x] = 0.0f;   // u(-1) = 0
        sb1[(rowbase + k) * NXX + x] = 0.0f;
    }

    int rmine = 0, roff = 0, obase = 0;
    if (tid < NREC) {
        const int ry = rec_y[tid];
        const int rx = rec_x[tid];
        rmine = (ry >= z0 && ry < z0 + ROWS);
        roff  = (ry - z0) * NXX + rx;
        obase = b * NREC + tid;
    }
    const float* xs = xsrc + b * NT;

    const int bk    = (half == 0) ? 0 : RPT - 1;   // my boundary slot
    const int bsrow = rowbase + bk;
    float hNb = 0.0f;                              // neighbor boundary u(t-1)

    __syncthreads();

    for (int t = 0; t < NT; t++) {
        const int rd = t & 1;
        float* __restrict__ rbuf = rd ? sb1 : sb0;   // u(t-1)
        float* __restrict__ wbuf = rd ? sb0 : sb1;   // receives u(t)
        const float xt = xs[t];

        // ---- Phase 1: boundary row u(t); publish immediately ----
        const float bOld = ucur[bk];
        {
            float lap = 0.0f;
            if (lapok & (1u << bk)) {
                const float vUp = (half == 0) ? hNb : rbuf[(bsrow - 1) * NXX + x];
                const float vDn = (half == 0) ? rbuf[(bsrow + 1) * NXX + x] : hNb;
                lap = (vUp + vDn + rbuf[bsrow * NXX + x - 1]
                               + rbuf[bsrow * NXX + x + 1]
                               - 4.0f * bOld) * inv_dh2;
            }
            float hn = 2.0f * bOld - uprev[bk] + c2[bk] * lap;
            if (smask & (1u << bk)) hn += xt;
            uprev[bk] = bOld;
            ucur[bk]  = hn;
            wbuf[bsrow * NXX + x] = hn;
            if (hasNb) {
                __stcg(&d_halo[rd][blk][half][x], hn);
                __threadfence();
            }
        }
        __syncthreads();
        if (tid == 0)
            *((volatile int*)&d_flags[blk]) = t + 1;   // u(t) boundary published

        // ---- Phase 2: interior rows u(t) (old-value carry; stores into wbuf) ----
        if (half == 0) {
            float carry = bOld;                        // old u(t-1)[row 0]
#pragma unroll
            for (int k = 1; k < RPT; k++) {
                const int srow = rowbase + k;
                const float uk = ucur[k];
                float lap = 0.0f;
                if (lapok & (1u << k)) {
                    const float dn = (k < RPT - 1) ? ucur[k + 1]
                                                   : rbuf[(srow + 1) * NXX + x];
                    lap = (carry + dn + rbuf[srow * NXX + x - 1]
                                      + rbuf[srow * NXX + x + 1]
                                      - 4.0f * uk) * inv_dh2;
                }
                float hn = 2.0f * uk - uprev[k] + c2[k] * lap;
                if (smask & (1u << k)) hn += xt;
                uprev[k] = uk;
                ucur[k]  = hn;
                wbuf[srow * NXX + x] = hn;
                carry = uk;
            }
        } else {
            float carry = rbuf[(rowbase - 1) * NXX + x];   // u(t-1)[row 5]
#pragma unroll
            for (int k = 0; k < RPT - 1; k++) {
                const int srow = rowbase + k;
                const float uk = ucur[k];
                float lap = 0.0f;
                if (lapok & (1u << k)) {
                    const float dn = (k < RPT - 2) ? ucur[k + 1] : bOld;
                    lap = (carry + dn + rbuf[srow * NXX + x - 1]
                                      + rbuf[srow * NXX + x + 1]
                                      - 4.0f * uk) * inv_dh2;
                }
                float hn = 2.0f * uk - uprev[k] + c2[k] * lap;
                if (smask & (1u << k)) hn += xt;
                uprev[k] = uk;
                ucur[k]  = hn;
                wbuf[srow * NXX + x] = hn;
                carry = uk;
            }
        }

        // ---- Phase 3: wait for neighbors' u(t) flags (posted ~a step ago) ----
        if (tid == 0 && topBlk >= 0) {
            while (*((volatile int*)&d_flags[topBlk]) < t + 1) { }
            __threadfence();
        }
        if (tid == NXX && botBlk >= 0) {
            while (*((volatile int*)&d_flags[botBlk]) < t + 1) { }
            __threadfence();
        }
        __syncthreads();

        // prefetch neighbor boundary u(t) for next iteration
        if (hasNb)
            hNb = __ldcg(&d_halo[rd][nb][half ^ 1][x]);

        // receiver gather for step t (wbuf complete after the bar)
        if (tid < NREC && rmine)
            out[t * (BB * NREC) + obase] = wbuf[roff];
    }
}

extern "C" void kernel_launch(void* const* d_in, const int* in_sizes, int n_in,
                              void* d_out, int out_size)
{
    const float* xsrc  = (const float*)d_in[0];
    const float* vp    = (const float*)d_in[1];
    const int*   src_y = (const int*)d_in[2];
    const int*   src_x = (const int*)d_in[3];
    const int*   rec_y = (const int*)d_in[4];
    const int*   rec_x = (const int*)d_in[5];
    float*       out   = (float*)d_out;

    zero_kernel<<<1, NBLK>>>();
    wave_kernel<<<NBLK, NTHR>>>(xsrc, vp, src_y, src_x, rec_y, rec_x, out);
}

// round 7
// speedup vs baseline: 2.2590x; 1.5425x over previous
#include <cuda_runtime.h>

#define BB 4
#define NT 256
#define NZ 384
#define NXX 384
#define NREC 128
#define DTc 0.001f
#define DHc 10.0f

#define NBLK 128
#define BLK_PER_B (NBLK / BB)      // 32 blocks per batch
#define ROWS 12                    // owned rows per block
#define RPT 6                      // rows per thread (2 halves)
#define NTHR (2 * NXX)             // 768 threads: thread = (column x, half)

// Packed halo word: hi32 = step counter (t+1 when u(t) published), lo32 = value bits.
// [slot = t&1][block][side: 0=top row,1=bottom row][x]
__device__ unsigned long long d_pack[2][NBLK][2][NXX];

__global__ void zero_kernel() {
    const int n = 2 * NBLK * 2 * NXX;
    for (int i = blockIdx.x * blockDim.x + threadIdx.x; i < n;
         i += gridDim.x * blockDim.x)
        ((unsigned long long*)d_pack)[i] = 0ull;
}

__device__ __forceinline__ void st_release_u64(unsigned long long* p,
                                               unsigned long long v) {
    asm volatile("st.release.gpu.global.u64 [%0], %1;" :: "l"(p), "l"(v) : "memory");
}
__device__ __forceinline__ unsigned long long ld_acquire_u64(
        const unsigned long long* p) {
    unsigned long long v;
    asm volatile("ld.acquire.gpu.global.u64 %0, [%1];" : "=l"(v) : "l"(p) : "memory");
    return v;
}

__global__ __launch_bounds__(NTHR, 1) void wave_kernel(
    const float* __restrict__ xsrc,   // [B, NT]
    const float* __restrict__ vp,     // [NZ, NX]
    const int*   __restrict__ src_y,
    const int*   __restrict__ src_x,
    const int*   __restrict__ rec_y,
    const int*   __restrict__ rec_x,
    float*       __restrict__ out)    // [NT, B, NREC]
{
    __shared__ float sb0[ROWS * NXX];
    __shared__ float sb1[ROWS * NXX];

    const int tid  = threadIdx.x;
    const int x    = tid % NXX;
    const int half = tid / NXX;             // warp-uniform (384 = 12 warps per half)
    const int blk  = blockIdx.x;
    const int b    = blk / BLK_PER_B;
    const int bib  = blk % BLK_PER_B;
    const int z0   = bib * ROWS;
    const int rowbase = half * RPT;
    const float inv_dh2 = 1.0f / (DHc * DHc);

    const int topBlk = (bib > 0) ? blk - 1 : -1;
    const int botBlk = (bib < BLK_PER_B - 1) ? blk + 1 : -1;
    const int nb     = (half == 0) ? topBlk : botBlk;     // outward neighbor
    const bool hasNb = (nb >= 0);

    const int sy = src_y[b];
    const int sx = src_x[b];

    float ucur[RPT], uprev[RPT], csc[RPT], srcf[RPT];

#pragma unroll
    for (int k = 0; k < RPT; k++) {
        const int zg = z0 + rowbase + k;
        ucur[k]  = 0.0f;
        uprev[k] = 0.0f;
        const float c = vp[zg * NXX + x] * DTc;
        const bool lok = (x > 0 && x < NXX - 1 && zg > 0 && zg < NZ - 1);
        csc[k]  = lok ? (c * c * inv_dh2) : 0.0f;
        srcf[k] = (zg == sy && x == sx) ? 1.0f : 0.0f;
        sb0[(rowbase + k) * NXX + x] = 0.0f;
        sb1[(rowbase + k) * NXX + x] = 0.0f;
    }

    int rmine = 0, roff = 0, obase = 0;
    if (tid < NREC) {
        const int ry = rec_y[tid];
        const int rx = rec_x[tid];
        rmine = (ry >= z0 && ry < z0 + ROWS);
        roff  = (ry - z0) * NXX + rx;
        obase = b * NREC + tid;
    }
    const float* xs = xsrc + b * NT;

    const int dxl = (x > 0) ? 1 : 0;              // clamped (value ×0 at edges)
    const int dxr = (x < NXX - 1) ? 1 : 0;
    const int pbase = rowbase * NXX + x;
    const int bk    = (half == 0) ? 0 : RPT - 1;  // boundary slot
    const int pb    = pbase + bk * NXX;

    float hNb = 0.0f;                              // neighbor boundary u(t-1)

    __syncthreads();

    for (int t = 0; t < NT; t++) {
        const int rd = t & 1;
        float* __restrict__ rbuf = rd ? sb1 : sb0;   // u(t-1)
        float* __restrict__ wbuf = rd ? sb0 : sb1;   // receives u(t)
        const float xt = xs[t];

        // receiver gather for step t-1 (rbuf holds u(t-1); prior bar ordered it)
        if (t > 0 && rmine)
            out[(t - 1) * (BB * NREC) + obase] = rbuf[roff];

        // ---- Phase 1: boundary row u(t); publish immediately (release) ----
        const float bOld = ucur[bk];
        {
            const float inner = (half == 0) ? ucur[1] : ucur[RPT - 2]; // old values
            const float vUp = (half == 0) ? hNb : inner;
            const float vDn = (half == 0) ? inner : hNb;
            const float lap = vUp + vDn + rbuf[pb - dxl] + rbuf[pb + dxr]
                              - 4.0f * bOld;
            float hn = fmaf(csc[bk], lap, 2.0f * bOld - uprev[bk]);
            hn = fmaf(srcf[bk], xt, hn);
            uprev[bk] = bOld;
            ucur[bk]  = hn;
            wbuf[pb]  = hn;
            if (hasNb) {
                const unsigned long long pk =
                    ((unsigned long long)(unsigned)(t + 1) << 32) |
                    (unsigned long long)__float_as_uint(hn);
                st_release_u64(&d_pack[rd][blk][half][x], pk);
            }
        }

        // ---- Phase 2: interior rows (old-value carry; branchless) ----
        if (half == 0) {
            float carry = bOld;
#pragma unroll
            for (int k = 1; k < RPT; k++) {
                const int pk = pbase + k * NXX;
                const float uk = ucur[k];
                const float dn = (k < RPT - 1) ? ucur[k + 1]
                                               : rbuf[pk + NXX];   // half1 row 6
                const float lap = carry + dn + rbuf[pk - dxl] + rbuf[pk + dxr]
                                  - 4.0f * uk;
                float hn = fmaf(csc[k], lap, 2.0f * uk - uprev[k]);
                hn = fmaf(srcf[k], xt, hn);
                uprev[k] = uk;
                ucur[k]  = hn;
                wbuf[pk] = hn;
                carry = uk;
            }
        } else {
            float carry = rbuf[pbase - NXX];                        // half0 row 5
#pragma unroll
            for (int k = 0; k < RPT - 1; k++) {
                const int pk = pbase + k * NXX;
                const float uk = ucur[k];
                const float dn = (k < RPT - 2) ? ucur[k + 1] : bOld;
                const float lap = carry + dn + rbuf[pk - dxl] + rbuf[pk + dxr]
                                  - 4.0f * uk;
                float hn = fmaf(csc[k], lap, 2.0f * uk - uprev[k]);
                hn = fmaf(srcf[k], xt, hn);
                uprev[k] = uk;
                ucur[k]  = hn;
                wbuf[pk] = hn;
                carry = uk;
            }
        }

        // ---- Phase 3: poll counterpart column for u(t) (acquire) ----
        if (hasNb && t < NT - 1) {
            unsigned long long v;
            do {
                v = ld_acquire_u64(&d_pack[rd][nb][half ^ 1][x]);
            } while ((int)(v >> 32) < t + 1);
            hNb = __uint_as_float((unsigned)v);
        }

        __syncthreads();   // wbuf complete; rbuf reads done before next overwrite
    }

    // ---- final receiver gather for t = NT-1 ----
    {
        float* last = ((NT - 1) & 1) ? sb0 : sb1;   // wbuf of final step
        if (rmine)
            out[(NT - 1) * (BB * NREC) + obase] = last[roff];
    }
}

extern "C" void kernel_launch(void* const* d_in, const int* in_sizes, int n_in,
                              void* d_out, int out_size)
{
    const float* xsrc  = (const float*)d_in[0];
    const float* vp    = (const float*)d_in[1];
    const int*   src_y = (const int*)d_in[2];
    const int*   src_x = (const int*)d_in[3];
    const int*   rec_y = (const int*)d_in[4];
    const int*   rec_x = (const int*)d_in[5];
    float*       out   = (float*)d_out;

    zero_kernel<<<128, 512>>>();
    wave_kernel<<<NBLK, NTHR>>>(xsrc, vp, src_y, src_x, rec_y, rec_x, out);
}

// round 8
// speedup vs baseline: 3.1586x; 1.3982x over previous
#include <cuda_runtime.h>

#define BB 4
#define NT 256
#define NZ 384
#define NXX 384
#define NREC 128
#define DTc 0.001f
#define DHc 10.0f

#define NBLK 128
#define BLK_PER_B (NBLK / BB)      // 32 blocks per batch
#define ROWS 12                    // owned rows per block
#define RPT 6                      // rows per thread (2 halves)
#define NTHR (2 * NXX)             // 768 threads: thread = (column x, half)

// Packed halo word: hi32 = step counter (t+1 when u(t) published), lo32 = value.
// Single-word atomicity of the 64-bit access IS the synchronization; the WAR on
// slot reuse is protected by the publish->consume data-dependency chain.
// [slot = t&1][block][side: 0=top row,1=bottom row][x]
__device__ unsigned long long d_pack[2][NBLK][2][NXX];

__global__ void zero_kernel() {
    const int n = 2 * NBLK * 2 * NXX;
    for (int i = blockIdx.x * blockDim.x + threadIdx.x; i < n;
         i += gridDim.x * blockDim.x)
        ((unsigned long long*)d_pack)[i] = 0ull;
}

__device__ __forceinline__ unsigned long long ld_vol_u64(
        const unsigned long long* p) {
    unsigned long long v;
    asm volatile("ld.volatile.global.u64 %0, [%1];" : "=l"(v) : "l"(p));
    return v;
}
__device__ __forceinline__ void st_vol_u64(unsigned long long* p,
                                           unsigned long long v) {
    asm volatile("st.volatile.global.u64 [%0], %1;" :: "l"(p), "l"(v));
}

__global__ __launch_bounds__(NTHR, 1) void wave_kernel(
    const float* __restrict__ xsrc,   // [B, NT]
    const float* __restrict__ vp,     // [NZ, NX]
    const int*   __restrict__ src_y,
    const int*   __restrict__ src_x,
    const int*   __restrict__ rec_y,
    const int*   __restrict__ rec_x,
    float*       __restrict__ out)    // [NT, B, NREC]
{
    __shared__ float sb0[ROWS * NXX];
    __shared__ float sb1[ROWS * NXX];

    const int tid  = threadIdx.x;
    const int x    = tid % NXX;
    const int half = tid / NXX;             // warp-uniform
    const int blk  = blockIdx.x;
    const int b    = blk / BLK_PER_B;
    const int bib  = blk % BLK_PER_B;
    const int z0   = bib * ROWS;
    const int rowbase = half * RPT;
    const float inv_dh2 = 1.0f / (DHc * DHc);

    const int topBlk = (bib > 0) ? blk - 1 : -1;
    const int botBlk = (bib < BLK_PER_B - 1) ? blk + 1 : -1;
    const int nb     = (half == 0) ? topBlk : botBlk;     // outward neighbor
    const bool hasNb = (nb >= 0);

    const int sy = src_y[b];
    const int sx = src_x[b];

    float ucur[RPT], uprev[RPT], csc[RPT], srcf[RPT];

#pragma unroll
    for (int k = 0; k < RPT; k++) {
        const int zg = z0 + rowbase + k;
        ucur[k]  = 0.0f;
        uprev[k] = 0.0f;
        const float c = vp[zg * NXX + x] * DTc;
        const bool lok = (x > 0 && x < NXX - 1 && zg > 0 && zg < NZ - 1);
        csc[k]  = lok ? (c * c * inv_dh2) : 0.0f;
        srcf[k] = (zg == sy && x == sx) ? 1.0f : 0.0f;
        sb0[(rowbase + k) * NXX + x] = 0.0f;
        sb1[(rowbase + k) * NXX + x] = 0.0f;
    }

    int rmine = 0, roff = 0;
    float* outp = out;
    if (tid < NREC) {
        const int ry = rec_y[tid];
        const int rx = rec_x[tid];
        rmine = (ry >= z0 && ry < z0 + ROWS);
        roff  = (ry - z0) * NXX + rx;
        outp  = out + b * NREC + tid;
    }
    const float* xs = xsrc + b * NT;

    const int pbase = rowbase * NXX + x;
    const int pL    = pbase - ((x > 0) ? 1 : 0);        // clamped left base
    const int pR    = pbase + ((x < NXX - 1) ? 1 : 0);  // clamped right base
    const int bk    = (half == 0) ? 0 : RPT - 1;        // my boundary slot

    // fixed handshake pointers (slot selected at compile time after unroll)
    unsigned long long* pub0  = &d_pack[0][blk][half][x];
    unsigned long long* pub1  = &d_pack[1][blk][half][x];
    const unsigned long long* pol0 = hasNb ? &d_pack[0][nb][half ^ 1][x] : pub0;
    const unsigned long long* pol1 = hasNb ? &d_pack[1][nb][half ^ 1][x] : pub1;

    float hNb = 0.0f;                                   // neighbor boundary u(t-1)

    __syncthreads();

    // One time step: rbuf holds u(t-1), wbuf receives u(t).
    #define STEP(T, RBUF, WBUF, PUBP, POLP)                                     \
    {                                                                           \
        const int   t  = (T);                                                   \
        const float xt = xs[t];                                                 \
        /* receiver gather for step t-1 (RBUF holds u(t-1)) */                  \
        if (t > 0 && rmine) { outp[(t - 1) * (BB * NREC)] = RBUF[roff]; }       \
        /* Phase 1: boundary row u(t); publish immediately */                   \
        const float bOld = ucur[bk];                                            \
        {                                                                       \
            const float inner = (half == 0) ? ucur[1] : ucur[RPT - 2];          \
            const float lap = hNb + inner + RBUF[pL + bk * NXX]                 \
                              + RBUF[pR + bk * NXX] - 4.0f * bOld;              \
            float hn = fmaf(csc[bk], lap, 2.0f * bOld - uprev[bk]);             \
            hn = fmaf(srcf[bk], xt, hn);                                        \
            uprev[bk] = bOld;                                                   \
            ucur[bk]  = hn;                                                     \
            WBUF[pbase + bk * NXX] = hn;                                        \
            if (hasNb) {                                                        \
                const unsigned long long pk =                                   \
                    ((unsigned long long)(unsigned)(t + 1) << 32) |             \
                    (unsigned long long)__float_as_uint(hn);                    \
                st_vol_u64(PUBP, pk);                                           \
            }                                                                   \
        }                                                                       \
        /* speculative poll: one load in flight during interior compute */      \
        unsigned long long spec = 0ull;                                         \
        if (hasNb && t < NT - 1) spec = ld_vol_u64(POLP);                       \
        /* Phase 2: interior rows (old-value carry; branchless) */              \
        if (half == 0) {                                                        \
            float carry = bOld;                                                 \
            _Pragma("unroll")                                                   \
            for (int k = 1; k < RPT; k++) {                                     \
                const float uk = ucur[k];                                       \
                const float dn = (k < RPT - 1) ? ucur[k + 1]                    \
                                               : RBUF[pbase + RPT * NXX];       \
                const float lap = carry + dn + RBUF[pL + k * NXX]               \
                                  + RBUF[pR + k * NXX] - 4.0f * uk;             \
                float hn = fmaf(csc[k], lap, 2.0f * uk - uprev[k]);             \
                hn = fmaf(srcf[k], xt, hn);                                     \
                uprev[k] = uk;                                                  \
                ucur[k]  = hn;                                                  \
                WBUF[pbase + k * NXX] = hn;                                     \
                carry = uk;                                                     \
            }                                                                   \
        } else {                                                                \
            float carry = RBUF[pbase - NXX];                                    \
            _Pragma("unroll")                                                   \
            for (int k = 0; k < RPT - 1; k++) {                                 \
                const float uk = ucur[k];                                       \
                const float dn = (k < RPT - 2) ? ucur[k + 1] : bOld;            \
                const float lap = carry + dn + RBUF[pL + k * NXX]               \
                                  + RBUF[pR + k * NXX] - 4.0f * uk;             \
                float hn = fmaf(csc[k], lap, 2.0f * uk - uprev[k]);             \
                hn = fmaf(srcf[k], xt, hn);                                     \
                uprev[k] = uk;                                                  \
                ucur[k]  = hn;                                                  \
                WBUF[pbase + k * NXX] = hn;                                     \
                carry = uk;                                                     \
            }                                                                   \
        }                                                                       \
        /* Phase 3: consume speculative poll (usually already valid) */         \
        if (hasNb && t < NT - 1) {                                              \
            unsigned long long v = spec;                                        \
            while ((int)(v >> 32) < t + 1) v = ld_vol_u64(POLP);                \
            hNb = __uint_as_float((unsigned)v);                                 \
        }                                                                       \
        __syncthreads();                                                        \
    }

#pragma unroll 1
    for (int tt = 0; tt < NT; tt += 2) {
        STEP(tt,     sb0, sb1, pub0, pol0)   // even t: slot 0
        STEP(tt + 1, sb1, sb0, pub1, pol1)   // odd  t: slot 1
    }
    #undef STEP

    // final receiver gather for t = NT-1 (last wbuf = sb0 since NT even)
    if (rmine)
        outp[(NT - 1) * (BB * NREC)] = sb0[roff];
}

extern "C" void kernel_launch(void* const* d_in, const int* in_sizes, int n_in,
                              void* d_out, int out_size)
{
    const float* xsrc  = (const float*)d_in[0];
    const float* vp    = (const float*)d_in[1];
    const int*   src_y = (const int*)d_in[2];
    const int*   src_x = (const int*)d_in[3];
    const int*   rec_y = (const int*)d_in[4];
    const int*   rec_x = (const int*)d_in[5];
    float*       out   = (float*)d_out;

    zero_kernel<<<128, 512>>>();
    wave_kernel<<<NBLK, NTHR>>>(xsrc, vp, src_y, src_x, rec_y, rec_x, out);
}